// round 9
// baseline (speedup 1.0000x reference)
#include <cuda_runtime.h>
#include <cstdint>

// p-bit Glauber sequential update, N=4096 spins, 16384 steps.
// K0: thr=atanh(2u-1) zipped with idx. K1: F0 = J@m0 + h. Kpack: per-window
// dense tables Jw[w][k][l]=J[idx(w,k)][idx(w,l)], Jc[w][k][l]=J[idx(w-1,k)][idx(w,l)].
// K2: 4-CTA CLUSTER, 544 thr/CTA.
//   - F is sharded: each CTA's 512 owner threads hold 2 floats (1024/CTA).
//   - CTA0 warp0 = evaluator: per window w, reads F at the 32 window indices
//     from a gather buffer (state w-2), catches up window w-1's flips via Jc,
//     resolves the window via Jw in smem (54cyc/flip chain), broadcasts the
//     flip list to all CTAs (DSMEM stores + release-arrive, count 32).
//   - owners: apply flip list (4KB/flip slice from L2), gather F values for
//     window p+2's indices from registers, relay warp DSMEM-stores them to
//     CTA0 + release-arrives on the gather mbarrier (count 32x4=128).
//   - 2-window pipeline slack => evaluator and owners overlap fully.

#define NN      4096
#define NSTEPS  16384
#define W       32
#define NWIN    (NSTEPS / W)      // 512
#define TPB     544
#define CSIZE   4
#define SLICE   (NN / CSIZE)      // 1024 floats per CTA
#define FULLM   0xffffffffu

__device__ float  g_F[NN];
__device__ float2 g_TI[NSTEPS];
__device__ float  g_Jw[NWIN * W * W];   // 2MB
__device__ float  g_Jc[NWIN * W * W];   // 2MB

// ---------------------------------------------------------------------------
__device__ __forceinline__ uint32_t smem_u32(const void* p) {
    uint32_t a;
    asm("{ .reg .u64 t; cvta.to.shared.u64 t, %1; cvt.u32.u64 %0, t; }"
        : "=r"(a) : "l"(p));
    return a;
}
__device__ __forceinline__ uint32_t ctarank() {
    uint32_t r;
    asm("mov.u32 %0, %%cluster_ctarank;" : "=r"(r));
    return r;
}
__device__ __forceinline__ void mbar_init(uint32_t a, uint32_t cnt) {
    asm volatile("mbarrier.init.shared.b64 [%0], %1;" :: "r"(a), "r"(cnt) : "memory");
}
__device__ __forceinline__ void mbar_wait_cl(uint32_t a, uint32_t parity) {
    asm volatile(
        "{\n\t.reg .pred P;\n\t"
        "WLP_%=:\n\t"
        "mbarrier.try_wait.parity.acquire.cluster.shared::cta.b64 P, [%0], %1, 0x989680;\n\t"
        "@P bra.uni WDN_%=;\n\t"
        "bra.uni WLP_%=;\n\t"
        "WDN_%=:\n\t}"
        :: "r"(a), "r"(parity) : "memory");
}
__device__ __forceinline__ void mbar_arrive_cl(uint32_t local_addr, uint32_t rank) {
    asm volatile(
        "{\n\t.reg .b32 ra;\n\t"
        "mapa.shared::cluster.u32 ra, %0, %1;\n\t"
        "mbarrier.arrive.release.cluster.shared::cluster.b64 _, [ra];\n\t}"
        :: "r"(local_addr), "r"(rank) : "memory");
}
__device__ __forceinline__ void st_remote_f32(uint32_t local_addr, uint32_t rank, float v) {
    asm volatile(
        "{\n\t.reg .b32 ra;\n\t"
        "mapa.shared::cluster.u32 ra, %0, %1;\n\t"
        "st.shared::cluster.f32 [ra], %2;\n\t}"
        :: "r"(local_addr), "r"(rank), "f"(v) : "memory");
}
__device__ __forceinline__ void st_remote_i32(uint32_t local_addr, uint32_t rank, int v) {
    asm volatile(
        "{\n\t.reg .b32 ra;\n\t"
        "mapa.shared::cluster.u32 ra, %0, %1;\n\t"
        "st.shared::cluster.b32 [ra], %2;\n\t}"
        :: "r"(local_addr), "r"(rank), "r"(v) : "memory");
}

// ---------------------------------------------------------------------------
__global__ void prep_thresholds(const int* __restrict__ idx,
                                const float* __restrict__ u) {
    const int t = blockIdx.x * blockDim.x + threadIdx.x;
    if (t < NSTEPS) {
        const float r = 2.0f * u[t] - 1.0f;
        g_TI[t] = make_float2(atanhf(r), __int_as_float(idx[t]));
    }
}

__global__ void pack_windows(const float* __restrict__ J,
                             const int* __restrict__ idx) {
    const int w = blockIdx.x;
    for (int e = threadIdx.x; e < W * W; e += blockDim.x) {
        const int k = e >> 5;
        const int l = e & 31;
        const int il = idx[w * W + l];
        const int ik = idx[w * W + k];
        g_Jw[w * W * W + e] = J[(size_t)ik * NN + il];
        float jc = 0.0f;
        if (w > 0) {
            const int ikp = idx[(w - 1) * W + k];
            jc = J[(size_t)ikp * NN + il];
        }
        g_Jc[w * W * W + e] = jc;
    }
}

__global__ void init_field(const float* __restrict__ J,
                           const float* __restrict__ h,
                           const float* __restrict__ m0) {
    const int row = blockIdx.x;
    const float4* __restrict__ Jr = reinterpret_cast<const float4*>(J) + (size_t)row * (NN / 4);
    const float4* __restrict__ M4 = reinterpret_cast<const float4*>(m0);

    float sum = 0.0f;
    for (int k = threadIdx.x; k < NN / 4; k += blockDim.x) {
        float4 a = Jr[k];
        float4 b = M4[k];
        sum += a.x * b.x + a.y * b.y + a.z * b.z + a.w * b.w;
    }
    #pragma unroll
    for (int off = 16; off; off >>= 1)
        sum += __shfl_xor_sync(FULLM, sum, off);

    __shared__ float ws[8];
    const int lane = threadIdx.x & 31;
    const int wid  = threadIdx.x >> 5;
    if (lane == 0) ws[wid] = sum;
    __syncthreads();
    if (threadIdx.x == 0) {
        float tot = 0.0f;
        #pragma unroll
        for (int w = 0; w < 8; w++) tot += ws[w];
        g_F[row] = tot + h[row];
    }
}

// ---------------------------------------------------------------------------
__global__ __launch_bounds__(TPB, 1) __cluster_dims__(CSIZE, 1, 1)
void pbit_dynamics(const float* __restrict__ J,
                   const float* __restrict__ m0,
                   float*       __restrict__ out) {
    __shared__ signed char m_s8[NN];        // CTA0 only (evaluator-owned)
    __shared__ float JwS[2][W * W];         // CTA0 only
    __shared__ float JcS[2][W * W];         // CTA0 only
    __shared__ float gatherBuf[2][W];       // CTA0 only (DSMEM target)
    __shared__ float gstage[2][W];          // per-CTA gather staging
    __shared__ int   idxS[2][W];            // next-window indices
    __shared__ int   flistBuf[2][W];
    __shared__ int   fcntBuf[2];
    __shared__ unsigned long long flipMbar;   // count 32
    __shared__ unsigned long long gathMbar;   // count 128 (CTA0)

    const int tid   = threadIdx.x;
    const int lane  = tid & 31;
    const uint32_t rank = ctarank();
    const bool is_ev   = (rank == 0) && (tid < 32);
    const bool is_own  = (tid >= 32);
    const bool is_rel  = (tid >= 32 && tid < 64);
    const int oid = tid - 32;               // owner index [0,512)

    const uint32_t fmAddr = smem_u32(&flipMbar);
    const uint32_t gmAddr = smem_u32(&gathMbar);

    if (tid == 0) {
        mbar_init(fmAddr, 32);
        if (rank == 0) mbar_init(gmAddr, 32 * CSIZE);
    }
    // owner F slice (2 floats per thread)
    const int gi0 = rank * SLICE + 2 * oid;
    const int gi1 = gi0 + 1;
    float Fx = 0.0f, Fy = 0.0f;
    if (is_own) {
        const float2 f2 = *reinterpret_cast<const float2*>(g_F + gi0);
        Fx = f2.x;
        Fy = f2.y;
    }
    if (rank == 0)
        for (int k = tid; k < NN; k += TPB)
            m_s8[k] = (m0[k] > 0.0f) ? 1 : -1;
    __syncthreads();
    asm volatile("barrier.cluster.arrive.aligned;" ::: "memory");
    asm volatile("barrier.cluster.wait.aligned;" ::: "memory");

    if (is_own) {
        // ---------------- prologue ----------------
        if (is_rel) {
            idxS[0][lane] = __float_as_int(g_TI[lane].y);          // window 0
            idxS[1][lane] = __float_as_int(g_TI[W + lane].y);      // window 1
        }
        if (rank == 0) {
            #pragma unroll
            for (int q = 0; q < 2; q++) {
                JwS[q][oid]       = g_Jw[q * (W * W) + oid];
                JwS[q][oid + 512] = g_Jw[q * (W * W) + oid + 512];
                JcS[q][oid]       = g_Jc[q * (W * W) + oid];
                JcS[q][oid + 512] = g_Jc[q * (W * W) + oid + 512];
            }
        }
        asm volatile("bar.sync 1, 512;" ::: "memory");
        #pragma unroll 8
        for (int l = 0; l < W; l++) {
            const int i0 = idxS[0][l];
            if (i0 == gi0) gstage[0][l] = Fx;
            if (i0 == gi1) gstage[0][l] = Fy;
            const int i1 = idxS[1][l];
            if (i1 == gi0) gstage[1][l] = Fx;
            if (i1 == gi1) gstage[1][l] = Fy;
        }
        asm volatile("bar.sync 1, 512;" ::: "memory");
        if (is_rel) {
            #pragma unroll
            for (int q = 0; q < 2; q++) {
                const int ix = idxS[q][lane];
                if ((unsigned)(ix - rank * SLICE) < (unsigned)SLICE)
                    st_remote_f32(smem_u32(&gatherBuf[q][lane]), 0, gstage[q][lane]);
                mbar_arrive_cl(gmAddr, 0);                 // phases 0 and 1
            }
            idxS[0][lane] = __float_as_int(g_TI[2 * W + lane].y);  // window 2
        }
        asm volatile("bar.sync 1, 512;" ::: "memory");

        // ---------------- main owner loop ----------------
        for (int p = 0; p < NWIN; p++) {
            const int par = p & 1;
            mbar_wait_cl(fmAddr, par);
            const int cnt = fcntBuf[par];
            for (int kb = 0; kb < cnt; kb += 4) {
                float dd[4];
                float2 v[4];
                #pragma unroll
                for (int j = 0; j < 4; j++) {
                    const bool valid = (kb + j < cnt);
                    const int e = valid ? flistBuf[par][kb + j] : 0;
                    dd[j] = valid ? ((e & (1 << 30)) ? 2.0f : -2.0f) : 0.0f;
                    const int ik = e & 0xFFFF;
                    v[j] = *reinterpret_cast<const float2*>(J + (size_t)ik * NN + gi0);
                }
                #pragma unroll
                for (int j = 0; j < 4; j++) {
                    Fx = fmaf(v[j].x, dd[j], Fx);
                    Fy = fmaf(v[j].y, dd[j], Fy);
                }
            }
            const bool hasG = (p + 2 < NWIN);
            if (hasG) {
                #pragma unroll 8
                for (int l = 0; l < W; l++) {
                    const int ix = idxS[par][l];
                    if (ix == gi0) gstage[par][l] = Fx;
                    if (ix == gi1) gstage[par][l] = Fy;
                }
                if (rank == 0) {
                    const float* __restrict__ sw = g_Jw + (size_t)(p + 2) * (W * W);
                    const float* __restrict__ sc = g_Jc + (size_t)(p + 2) * (W * W);
                    JwS[par][oid]       = sw[oid];
                    JwS[par][oid + 512] = sw[oid + 512];
                    JcS[par][oid]       = sc[oid];
                    JcS[par][oid + 512] = sc[oid + 512];
                }
            }
            if (is_rel && p + 3 < NWIN)
                idxS[par ^ 1][lane] = __float_as_int(g_TI[(p + 3) * W + lane].y);
            asm volatile("bar.sync 1, 512;" ::: "memory");
            if (is_rel && hasG) {
                const int ix = idxS[par][lane];
                if ((unsigned)(ix - rank * SLICE) < (unsigned)SLICE)
                    st_remote_f32(smem_u32(&gatherBuf[par][lane]), 0, gstage[par][lane]);
                mbar_arrive_cl(gmAddr, 0);
            }
        }
    } else if (is_ev) {
        // ---------------- evaluator warp (CTA0 warp 0) ----------------
        float2 tiPF = g_TI[lane];
        unsigned prevFlipM = 0, prevSignM = 0;

        for (int w = 0; w < NWIN; w++) {
            const int par = w & 1;
            mbar_wait_cl(gmAddr, par);
            __syncwarp();
            float fF = gatherBuf[par][lane];
            const float my_thr = tiPF.x;
            const int   my_i   = __float_as_int(tiPF.y);
            if (w + 1 < NWIN) tiPF = g_TI[(w + 1) * W + lane];

            // catch up window w-1's flips (ascending order == owner order)
            {
                const float* JcP = JcS[par];
                unsigned mm = prevFlipM;
                while (mm) {
                    const int k = __ffs(mm) - 1;
                    mm &= mm - 1;
                    const float dk = ((prevSignM >> k) & 1u) ? 2.0f : -2.0f;
                    fF = fmaf(JcP[(k << 5) + lane], dk, fF);
                }
            }

            bool my_pos = (m_s8[my_i] > 0);
            bool spos = (fF >= my_thr);
            bool flip = spos != my_pos;
            unsigned fb  = __ballot_sync(FULLM, flip);
            unsigned sbm = __ballot_sync(FULLM, spos);

            const float* JwP = JwS[par];
            unsigned flipM = 0, signM = 0;
            int cnt = 0;
            while (fb) {
                const int  f1 = __ffs(fb) - 1;
                const bool s1pos = (sbm >> f1) & 1u;
                const float d = s1pos ? 2.0f : -2.0f;
                const float jv = JwP[(f1 << 5) + lane];
                const int   i1 = __shfl_sync(FULLM, my_i, f1);
                if (lane == f1) {
                    m_s8[i1] = s1pos ? 1 : -1;
                    flistBuf[par][cnt] = i1 | (s1pos ? (1 << 30) : 0);
                }
                flipM |= (1u << f1);
                if (s1pos) signM |= (1u << f1);
                cnt++;

                fF = fmaf(jv, d, fF);
                if (my_i == i1) my_pos = s1pos;
                bool ns = false, nf = false;
                if (lane > f1) {
                    ns = (fF >= my_thr);
                    nf = ns != my_pos;
                }
                fb  = __ballot_sync(FULLM, nf);
                sbm = __ballot_sync(FULLM, ns);
            }
            __syncwarp();
            // broadcast flip list + count to peers, then release-arrive everywhere
            if (lane < cnt) {
                const int e = flistBuf[par][lane];
                #pragma unroll
                for (int r = 1; r < CSIZE; r++)
                    st_remote_i32(smem_u32(&flistBuf[par][lane]), r, e);
            }
            if (lane == 0) {
                fcntBuf[par] = cnt;
                #pragma unroll
                for (int r = 1; r < CSIZE; r++)
                    st_remote_i32(smem_u32(&fcntBuf[par]), r, cnt);
            }
            #pragma unroll
            for (int r = 0; r < CSIZE; r++)
                mbar_arrive_cl(fmAddr, r);

            prevFlipM = flipM;
            prevSignM = signM;
        }
    }

    if (rank == 0) {
        __syncthreads();
        for (int k = tid; k < NN; k += TPB)
            out[k] = (float)m_s8[k];
    }
}

// ---------------------------------------------------------------------------
extern "C" void kernel_launch(void* const* d_in, const int* in_sizes, int n_in,
                              void* d_out, int out_size) {
    const float* J  = (const float*)d_in[0];
    const float* h  = (const float*)d_in[1];
    const float* m0 = (const float*)d_in[2];
    const int*   idx= (const int*)  d_in[3];
    const float* u  = (const float*)d_in[4];
    float* out = (float*)d_out;

    prep_thresholds<<<NSTEPS / 256, 256>>>(idx, u);
    pack_windows<<<NWIN, 256>>>(J, idx);
    init_field<<<NN, 256>>>(J, h, m0);
    pbit_dynamics<<<CSIZE, TPB>>>(J, m0, out);
}

// round 10
// speedup vs baseline: 2.2301x; 2.2301x over previous
#include <cuda_runtime.h>
#include <cstdint>

// p-bit Glauber sequential update, N=4096 spins, 16384 steps.
// prep_all (one launch, grid-partitioned):
//   rows 0..4095:      F0 = J@m0 + h
//   next 256 blocks:   pack per-window tables (W=64):
//       Jw[w][k][l] = J[idx(w,k)][idx(w,l)]   (within-window)
//       Jc[w][k][l] = J[idx(w-1,k)][idx(w,l)] (cross-window catch-up)
//   last 64 blocks:    thr[t] = atanh(2u-1) zipped with idx[t]
// pbit_dynamics: single CTA, 544 threads, warp-specialized, W=64 windows:
//   evaluator (warp 0): resolves window w (two 32-step halves) purely from
//     smem tables; catch-up of window w-1 flips via Jc (ascending order ==
//     owner order -> bit-identical fmaf). Writes flip list.
//   owners (512 thr, F in registers, 8 elems/thread): issue staging LDGs for
//     window w+1 tables, apply window w-1's flip list (rank-1 rows, batch 4),
//     store staging, handshake on named barrier 1, publish F_sh.
//   ONE __syncthreads per window; 256 windows.

#define NN      4096
#define NSTEPS  16384
#define W       64
#define NWIN    (NSTEPS / W)      // 256
#define TPB     544
#define NOWN    512
#define FULLM   0xffffffffu

__device__ float  g_F[NN];
__device__ float2 g_TI[NSTEPS];
__device__ float  g_Jw[NWIN * W * W];   // 4MB
__device__ float  g_Jc[NWIN * W * W];   // 4MB

struct SmemLayout {
    float F[NN];              // 16KB
    float Jw[2][W * W];       // 32KB
    float Jc[2][W * W];       // 32KB
    float mF[NN];             // unused pad avoidance? (not used)
    signed char m[NN];        // 4KB
    int   flist[2][W];
    int   fcnt[2];
};
// NOTE: mF removed below via second struct; keep layout lean:
struct Sm {
    float F[NN];              // 16KB
    float Jw[2][W * W];       // 32KB
    float Jc[2][W * W];       // 32KB
    signed char m[NN];        // 4KB
    int   flist[2][W];
    int   fcnt[2];
};
#define SMEM_BYTES ((int)sizeof(Sm))

// ---------------------------------------------------------------------------
// fused prep: init_field rows | pack_windows | thresholds
// ---------------------------------------------------------------------------
__global__ void prep_all(const float* __restrict__ J,
                         const float* __restrict__ h,
                         const float* __restrict__ m0,
                         const int*   __restrict__ idx,
                         const float* __restrict__ u) {
    const int bid = blockIdx.x;
    if (bid < NN) {
        // ---- init_field row ----
        const int row = bid;
        const float4* __restrict__ Jr =
            reinterpret_cast<const float4*>(J) + (size_t)row * (NN / 4);
        const float4* __restrict__ M4 = reinterpret_cast<const float4*>(m0);
        float sum = 0.0f;
        for (int k = threadIdx.x; k < NN / 4; k += blockDim.x) {
            float4 a = Jr[k];
            float4 b = M4[k];
            sum += a.x * b.x + a.y * b.y + a.z * b.z + a.w * b.w;
        }
        #pragma unroll
        for (int off = 16; off; off >>= 1)
            sum += __shfl_xor_sync(FULLM, sum, off);
        __shared__ float ws[8];
        const int lane = threadIdx.x & 31;
        const int wid  = threadIdx.x >> 5;
        if (lane == 0) ws[wid] = sum;
        __syncthreads();
        if (threadIdx.x == 0) {
            float tot = 0.0f;
            #pragma unroll
            for (int w = 0; w < 8; w++) tot += ws[w];
            g_F[row] = tot + h[row];
        }
    } else if (bid < NN + NWIN) {
        // ---- pack window tables ----
        const int w = bid - NN;
        for (int e = threadIdx.x; e < W * W; e += blockDim.x) {
            const int k = e >> 6;
            const int l = e & 63;
            const int il = idx[w * W + l];
            const int ik = idx[w * W + k];
            g_Jw[(size_t)w * W * W + e] = J[(size_t)ik * NN + il];
            float jc = 0.0f;
            if (w > 0) {
                const int ikp = idx[(w - 1) * W + k];
                jc = J[(size_t)ikp * NN + il];
            }
            g_Jc[(size_t)w * W * W + e] = jc;
        }
    } else {
        // ---- thresholds ----
        const int t = (bid - NN - NWIN) * blockDim.x + threadIdx.x;
        if (t < NSTEPS) {
            const float r = 2.0f * u[t] - 1.0f;
            g_TI[t] = make_float2(atanhf(r), __int_as_float(idx[t]));
        }
    }
}

// ---------------------------------------------------------------------------
__global__ __launch_bounds__(TPB, 1)
void pbit_dynamics(const float* __restrict__ J,
                   const float* __restrict__ m0,
                   float*       __restrict__ out) {
    extern __shared__ char smraw[];
    Sm* S = reinterpret_cast<Sm*>(smraw);

    const int tid  = threadIdx.x;
    const int lane = tid & 31;
    const bool is_ev = (tid < 32);
    const int oid  = tid - 32;      // owner index [0,512)

    // ---- init ----
    const float4* gF4 = reinterpret_cast<const float4*>(g_F);
    float4* F4 = reinterpret_cast<float4*>(S->F);
    float4 Fa, Fb;
    if (!is_ev) {
        Fa = gF4[oid];
        Fb = gF4[oid + NOWN];
        F4[oid]        = Fa;
        F4[oid + NOWN] = Fb;
    }
    for (int k = tid; k < NN; k += TPB)
        S->m[k] = (m0[k] > 0.0f) ? 1 : -1;
    if (tid == 0) { S->fcnt[0] = 0; S->fcnt[1] = 0; }
    for (int e = tid; e < W * W; e += TPB) {       // stage window 0
        S->Jw[0][e] = g_Jw[e];
        S->Jc[0][e] = g_Jc[e];
    }
    float2 tiPF0 = make_float2(0.f, 0.f), tiPF1 = tiPF0;
    if (is_ev) {
        tiPF0 = g_TI[lane];
        tiPF1 = g_TI[32 + lane];
    }
    unsigned prevM0 = 0, prevS0 = 0, prevM1 = 0, prevS1 = 0;
    __syncthreads();

    for (int p = 0; p < NWIN; p++) {
        const int par = p & 1;
        if (is_ev) {
            // ================= evaluator =================
            const float thr0 = tiPF0.x;
            const int   i0   = __float_as_int(tiPF0.y);
            const float thr1 = tiPF1.x;
            const int   i1x  = __float_as_int(tiPF1.y);
            float f0  = S->F[i0];            // state <= p-2
            float f1v = S->F[i1x];
            bool pos0 = (S->m[i0]  > 0);
            bool pos1 = (S->m[i1x] > 0);
            asm volatile("bar.arrive 1, %0;" :: "r"(TPB));   // release F_sh

            if (p + 1 < NWIN) {
                tiPF0 = g_TI[(p + 1) * W + lane];
                tiPF1 = g_TI[(p + 1) * W + 32 + lane];
            }

            // ---- catch up window p-1's flips (ascending step order) ----
            const float* JcP = S->Jc[par];
            {
                unsigned mm = prevM0;
                while (mm) {
                    const int k = __ffs(mm) - 1;
                    mm &= mm - 1;
                    const float dk = ((prevS0 >> k) & 1u) ? 2.0f : -2.0f;
                    f0  = fmaf(JcP[(k << 6) + lane],      dk, f0);
                    f1v = fmaf(JcP[(k << 6) + 32 + lane], dk, f1v);
                }
                mm = prevM1;
                while (mm) {
                    const int k = __ffs(mm) - 1;
                    mm &= mm - 1;
                    const int r = 32 + k;
                    const float dk = ((prevS1 >> k) & 1u) ? 2.0f : -2.0f;
                    f0  = fmaf(JcP[(r << 6) + lane],      dk, f0);
                    f1v = fmaf(JcP[(r << 6) + 32 + lane], dk, f1v);
                }
            }

            const float* JwP = S->Jw[par];
            unsigned nM0 = 0, nS0 = 0, nM1 = 0, nS1 = 0;
            int cnt = 0;

            // ---- half A: steps 0..31 ----
            {
                bool sp = (f0 >= thr0);
                bool fl = sp != pos0;
                unsigned fb  = __ballot_sync(FULLM, fl);
                unsigned sbm = __ballot_sync(FULLM, sp);
                while (fb) {
                    const int  f = __ffs(fb) - 1;
                    const bool s1 = (sbm >> f) & 1u;
                    const float d = s1 ? 2.0f : -2.0f;
                    const float jva = JwP[(f << 6) + lane];
                    const float jvb = JwP[(f << 6) + 32 + lane];
                    const int   ii  = __shfl_sync(FULLM, i0, f);
                    if (lane == f) {
                        S->m[ii] = s1 ? 1 : -1;
                        S->flist[par][cnt] = ii | (s1 ? (1 << 30) : 0);
                    }
                    nM0 |= 1u << f;
                    if (s1) nS0 |= 1u << f;
                    cnt++;
                    f0  = fmaf(jva, d, f0);
                    f1v = fmaf(jvb, d, f1v);
                    if (i0  == ii) pos0 = s1;
                    if (i1x == ii) pos1 = s1;
                    bool ns = false, nf2 = false;
                    if (lane > f) {
                        ns  = (f0 >= thr0);
                        nf2 = ns != pos0;
                    }
                    fb  = __ballot_sync(FULLM, nf2);
                    sbm = __ballot_sync(FULLM, ns);
                }
            }
            // ---- half B: steps 32..63 ----
            {
                bool sp = (f1v >= thr1);
                bool fl = sp != pos1;
                unsigned fb  = __ballot_sync(FULLM, fl);
                unsigned sbm = __ballot_sync(FULLM, sp);
                while (fb) {
                    const int  f = __ffs(fb) - 1;
                    const bool s1 = (sbm >> f) & 1u;
                    const float d = s1 ? 2.0f : -2.0f;
                    const int  r = 32 + f;
                    const float jvb = JwP[(r << 6) + 32 + lane];
                    const int   ii  = __shfl_sync(FULLM, i1x, f);
                    if (lane == f) {
                        S->m[ii] = s1 ? 1 : -1;
                        S->flist[par][cnt] = ii | (s1 ? (1 << 30) : 0);
                    }
                    nM1 |= 1u << f;
                    if (s1) nS1 |= 1u << f;
                    cnt++;
                    f1v = fmaf(jvb, d, f1v);
                    if (i1x == ii) pos1 = s1;
                    bool ns = false, nf2 = false;
                    if (lane > f) {
                        ns  = (f1v >= thr1);
                        nf2 = ns != pos1;
                    }
                    fb  = __ballot_sync(FULLM, nf2);
                    sbm = __ballot_sync(FULLM, ns);
                }
            }
            if (lane == 0) S->fcnt[par] = cnt;
            prevM0 = nM0; prevS0 = nS0;
            prevM1 = nM1; prevS1 = nS1;
        } else {
            // ================= owners =================
            // issue staging loads for window p+1 FIRST (latency hidden by apply)
            float4 sw0, sw1, sc0, sc1;
            const bool hasStage = (p + 1 < NWIN);
            if (hasStage) {
                const float4* __restrict__ sw =
                    reinterpret_cast<const float4*>(g_Jw + (size_t)(p + 1) * (W * W));
                const float4* __restrict__ sc =
                    reinterpret_cast<const float4*>(g_Jc + (size_t)(p + 1) * (W * W));
                sw0 = sw[oid]; sw1 = sw[oid + NOWN];
                sc0 = sc[oid]; sc1 = sc[oid + NOWN];
            }

            // apply window p-1's flips
            const int np = S->fcnt[par ^ 1];
            for (int kb = 0; kb < np; kb += 4) {
                float  dd[4];
                float4 r0[4], r1[4];
                #pragma unroll
                for (int j = 0; j < 4; j++) {
                    const bool v = (kb + j < np);
                    const int e = v ? S->flist[par ^ 1][kb + j] : 0;
                    dd[j] = v ? ((e & (1 << 30)) ? 2.0f : -2.0f) : 0.0f;
                    const int ik = e & 0xFFFF;
                    const float4* __restrict__ Jr =
                        reinterpret_cast<const float4*>(J) + (size_t)ik * (NN / 4);
                    if (v) {
                        r0[j] = Jr[oid];
                        r1[j] = Jr[oid + NOWN];
                    } else {
                        r0[j] = make_float4(0.f, 0.f, 0.f, 0.f);
                        r1[j] = r0[j];
                    }
                }
                #pragma unroll
                for (int j = 0; j < 4; j++) {
                    Fa.x = fmaf(r0[j].x, dd[j], Fa.x);
                    Fa.y = fmaf(r0[j].y, dd[j], Fa.y);
                    Fa.z = fmaf(r0[j].z, dd[j], Fa.z);
                    Fa.w = fmaf(r0[j].w, dd[j], Fa.w);
                    Fb.x = fmaf(r1[j].x, dd[j], Fb.x);
                    Fb.y = fmaf(r1[j].y, dd[j], Fb.y);
                    Fb.z = fmaf(r1[j].z, dd[j], Fb.z);
                    Fb.w = fmaf(r1[j].w, dd[j], Fb.w);
                }
            }

            // store staging into the buffer freed last window
            if (hasStage) {
                float4* dw = reinterpret_cast<float4*>(S->Jw[par ^ 1]);
                float4* dc = reinterpret_cast<float4*>(S->Jc[par ^ 1]);
                dw[oid] = sw0; dw[oid + NOWN] = sw1;
                dc[oid] = sc0; dc[oid + NOWN] = sc1;
            }

            // wait for evaluator's F_sh reads, then publish
            asm volatile("bar.sync 1, %0;" :: "r"(TPB));
            if (np > 0) {
                F4[oid]        = Fa;
                F4[oid + NOWN] = Fb;
            }
        }
        __syncthreads();
    }

    for (int k = tid; k < NN; k += TPB)
        out[k] = (float)S->m[k];
}

// ---------------------------------------------------------------------------
extern "C" void kernel_launch(void* const* d_in, const int* in_sizes, int n_in,
                              void* d_out, int out_size) {
    const float* J  = (const float*)d_in[0];
    const float* h  = (const float*)d_in[1];
    const float* m0 = (const float*)d_in[2];
    const int*   idx= (const int*)  d_in[3];
    const float* u  = (const float*)d_in[4];
    float* out = (float*)d_out;

    static bool attrSet = false;
    if (!attrSet) {
        cudaFuncSetAttribute(pbit_dynamics,
                             cudaFuncAttributeMaxDynamicSharedMemorySize,
                             SMEM_BYTES);
        attrSet = true;
    }

    const int prepBlocks = NN + NWIN + (NSTEPS + 255) / 256;
    prep_all<<<prepBlocks, 256>>>(J, h, m0, idx, u);
    pbit_dynamics<<<1, TPB, SMEM_BYTES>>>(J, m0, out);
}